// round 13
// baseline (speedup 1.0000x reference)
#include <cuda_runtime.h>
#include <cuda_fp16.h>
#include <cstdint>

#define N_NODES 50000
#define N_EDGES 800000
#define F 64
#define TILE_M 128
#define ROW_STRIDE 132      // f32 stride of staged rows
#define WS_STRIDE 72        // float2 stride of W hi/lo in smem
#define SCAN_BLOCKS 196

// Scratch (allocation-free: __device__ globals)
__device__ int    g_deg[N_NODES];        // invariant: zero on entry (scan restores)
__device__ int    g_off[N_NODES + 1];
__device__ int    g_cur[N_NODES];
__device__ int    g_csr[N_EDGES];
__device__ int    g_blk_agg[SCAN_BLOCKS];
__device__ int    g_blk_pfx[SCAN_BLOCKS];
__device__ int    g_blk_st[SCAN_BLOCKS]; // 0 invalid / 1 agg / 2 prefix
__device__ float  g_h[N_NODES * F];
__device__ float  g_agg[N_NODES * F];
__device__ __half g_half[N_NODES * F];   // fp16 mirror of gather source
__device__ float2 g_ws1[128 * 64];       // W1 hi/lo split (3xTF32)
__device__ float2 g_ws2[128 * 64];       // W2 hi/lo split
__device__ int    g_is64;

__device__ __forceinline__ int load_idx(const void* ei, int i, int is64) {
    if (is64) return (int)((const long long*)ei)[i];
    return ((const int*)ei)[i];
}

__device__ __forceinline__ unsigned tf32_hi(float a) {
    unsigned r;
    asm("cvt.rna.tf32.f32 %0, %1;" : "=r"(r) : "f"(a));
    return r;
}

// ---------------------------------------------------------------------------
// Prep: warp-cooperative dtype detect + degree histogram + x->fp16 mirror +
// W1/W2 hi/lo split + scan-status reset. Requires g_deg == 0 on entry.
// ---------------------------------------------------------------------------
__global__ void prep_kernel(const void* __restrict__ ei,
                            const float* __restrict__ x,
                            const float* __restrict__ W1,
                            const float* __restrict__ W2) {
    int i = blockIdx.x * blockDim.x + threadIdx.x;
    int lane = threadIdx.x & 31;

    // Warp-cooperative detect: one cached 8B load per lane, ballot combine.
    long long v = ((const long long*)ei)[lane & 15];
    unsigned m = __ballot_sync(0xffffffffu, v >= 0 && v < N_NODES);
    int is64 = ((m & 0xffffu) == 0xffffu) && ((m >> 16) == 0xffffu);
    if (i == 0) g_is64 = is64;

    if (i < SCAN_BLOCKS) g_blk_st[i] = 0;

    if (i < N_EDGES) {
        int d = load_idx(ei, N_EDGES + i, is64);
        if ((unsigned)d < N_NODES) atomicAdd(&g_deg[d], 1);
    }
    if (i < N_NODES * F / 2) {
        float2 xv = ((const float2*)x)[i];
        ((__half2*)g_half)[i] = __floats2half2_rn(xv.x, xv.y);
    }
    if (i < 2 * 128 * 64) {
        const float* Wsel = (i < 128 * 64) ? W1 : W2;
        float2* dst = (i < 128 * 64) ? g_ws1 : g_ws2;
        int idx = i & (128 * 64 - 1);
        float w = Wsel[idx];
        unsigned hb = tf32_hi(w);
        float hf = __uint_as_float(hb);
        unsigned lb = tf32_hi(w - hf);
        dst[idx] = make_float2(hf, __uint_as_float(lb));
    }
}

// ---------------------------------------------------------------------------
// Single-kernel exclusive scan (decoupled lookback), 196 blocks x 256.
// All blocks co-resident (tiny kernel) -> lookback is deadlock-free.
// Also restores g_deg = 0 and zeroes g_cur.
// ---------------------------------------------------------------------------
__global__ void __launch_bounds__(256)
scan_kernel() {
    __shared__ int sh[256];
    __shared__ int s_pfx;
    int t = threadIdx.x, b = blockIdx.x;
    int i = b * 256 + t;

    int v = (i < N_NODES) ? g_deg[i] : 0;
    sh[t] = v;
    __syncthreads();
    #pragma unroll
    for (int ofs = 1; ofs < 256; ofs <<= 1) {
        int add = (t >= ofs) ? sh[t - ofs] : 0;
        __syncthreads();
        sh[t] += add;
        __syncthreads();
    }
    int total = sh[255];

    if (t == 0) {
        volatile int* vagg = g_blk_agg;
        volatile int* vpfx = g_blk_pfx;
        if (b == 0) {
            g_blk_pfx[0] = total;
            __threadfence();
            atomicExch(&g_blk_st[0], 2);
            s_pfx = 0;
        } else {
            g_blk_agg[b] = total;
            __threadfence();
            atomicExch(&g_blk_st[b], 1);
            int pfx = 0;
            int j = b - 1;
            while (j >= 0) {
                int st;
                do { st = atomicAdd(&g_blk_st[j], 0); } while (st == 0);
                if (st == 2) { pfx += vpfx[j]; break; }
                pfx += vagg[j];
                j--;
            }
            g_blk_pfx[b] = pfx + total;
            __threadfence();
            atomicExch(&g_blk_st[b], 2);
            s_pfx = pfx;
        }
    }
    __syncthreads();
    int pfx = s_pfx;
    if (i < N_NODES) {
        g_off[i + 1] = sh[t] + pfx;
        g_deg[i] = 0;     // restore invariant for next call
        g_cur[i] = 0;     // fill precondition
    }
    if (i == 0) g_off[0] = 0;
}

// ---------------------------------------------------------------------------
__global__ void fill_kernel(const void* __restrict__ ei) {
    int e = blockIdx.x * blockDim.x + threadIdx.x;
    if (e >= N_EDGES) return;
    int is64 = g_is64;
    int s = load_idx(ei, e, is64);
    int d = load_idx(ei, N_EDGES + e, is64);
    if ((unsigned)s >= N_NODES || (unsigned)d >= N_NODES) return;
    int pos = atomicAdd(&g_cur[d], 1);
    g_csr[g_off[d] + pos] = s;
}

// ---------------------------------------------------------------------------
// CSR mean-aggregation from fp16 mirror -> g_agg (f32). (R12, proven)
// ---------------------------------------------------------------------------
__global__ void __launch_bounds__(256)
agg_kernel() {
    int warp = threadIdx.x >> 5, lane = threadIdx.x & 31;
    int n = blockIdx.x * 8 + warp;
    if (n >= N_NODES) return;
    int slot  = lane >> 3;
    int fpart = lane & 7;

    const uint4* xh4 = (const uint4*)g_half;

    int e0 = g_off[n], e1 = g_off[n + 1];
    float2 a0 = make_float2(0.f, 0.f), a1 = a0, a2 = a0, a3 = a0;

    int e = e0 + slot;
    for (; e + 4 < e1; e += 8) {
        int s0 = g_csr[e];
        int s1 = g_csr[e + 4];
        uint4 u0 = xh4[s0 * 8 + fpart];
        uint4 u1 = xh4[s1 * 8 + fpart];
        float2 p;
        p = __half22float2(*(__half2*)&u0.x); a0.x += p.x; a0.y += p.y;
        p = __half22float2(*(__half2*)&u0.y); a1.x += p.x; a1.y += p.y;
        p = __half22float2(*(__half2*)&u0.z); a2.x += p.x; a2.y += p.y;
        p = __half22float2(*(__half2*)&u0.w); a3.x += p.x; a3.y += p.y;
        p = __half22float2(*(__half2*)&u1.x); a0.x += p.x; a0.y += p.y;
        p = __half22float2(*(__half2*)&u1.y); a1.x += p.x; a1.y += p.y;
        p = __half22float2(*(__half2*)&u1.z); a2.x += p.x; a2.y += p.y;
        p = __half22float2(*(__half2*)&u1.w); a3.x += p.x; a3.y += p.y;
    }
    if (e < e1) {
        int s0 = g_csr[e];
        uint4 u0 = xh4[s0 * 8 + fpart];
        float2 p;
        p = __half22float2(*(__half2*)&u0.x); a0.x += p.x; a0.y += p.y;
        p = __half22float2(*(__half2*)&u0.y); a1.x += p.x; a1.y += p.y;
        p = __half22float2(*(__half2*)&u0.z); a2.x += p.x; a2.y += p.y;
        p = __half22float2(*(__half2*)&u0.w); a3.x += p.x; a3.y += p.y;
    }

    #pragma unroll
    for (int m = 8; m <= 16; m <<= 1) {
        a0.x += __shfl_xor_sync(0xffffffffu, a0.x, m);
        a0.y += __shfl_xor_sync(0xffffffffu, a0.y, m);
        a1.x += __shfl_xor_sync(0xffffffffu, a1.x, m);
        a1.y += __shfl_xor_sync(0xffffffffu, a1.y, m);
        a2.x += __shfl_xor_sync(0xffffffffu, a2.x, m);
        a2.y += __shfl_xor_sync(0xffffffffu, a2.y, m);
        a3.x += __shfl_xor_sync(0xffffffffu, a3.x, m);
        a3.y += __shfl_xor_sync(0xffffffffu, a3.y, m);
    }

    if (slot == 0) {
        float inv = 1.0f / fmaxf((float)(e1 - e0), 1.0f);
        float4* dst = (float4*)(g_agg + n * 64 + fpart * 8);
        dst[0] = make_float4(a0.x * inv, a0.y * inv, a1.x * inv, a1.y * inv);
        dst[1] = make_float4(a2.x * inv, a2.y * inv, a3.x * inv, a3.y * inv);
    }
}

// ---------------------------------------------------------------------------
// Tensor-core GEMM (3xTF32): out = [x || agg] @ W + b (+ReLU)  (proven)
// ---------------------------------------------------------------------------
__device__ __forceinline__ void mma_tf32(float* c, unsigned a0, unsigned a1,
                                         unsigned a2, unsigned a3,
                                         unsigned b0, unsigned b1) {
    asm volatile(
        "mma.sync.aligned.m16n8k8.row.col.f32.tf32.tf32.f32 "
        "{%0,%1,%2,%3}, {%4,%5,%6,%7}, {%8,%9}, {%0,%1,%2,%3};"
        : "+f"(c[0]), "+f"(c[1]), "+f"(c[2]), "+f"(c[3])
        : "r"(a0), "r"(a1), "r"(a2), "r"(a3), "r"(b0), "r"(b1));
}

__global__ void __launch_bounds__(256)
gemm_kernel(const float* __restrict__ xin, const float2* __restrict__ Wsplit,
            const float* __restrict__ bias, float* __restrict__ out,
            int relu, int to_half) {
    extern __shared__ float sm[];
    float*  row = sm;
    float2* Ws2 = (float2*)(sm + TILE_M * ROW_STRIDE);

    int tid = threadIdx.x;

    const float4* wsrc = (const float4*)Wsplit;
    #pragma unroll
    for (int i = 0; i < 16; i++) {
        int j = tid + i * 256;
        int f2 = j * 2;
        int k = f2 >> 6, c = f2 & 63;
        *(float4*)&Ws2[k * WS_STRIDE + c] = wsrc[j];
    }

    int base = blockIdx.x * TILE_M;
    #pragma unroll
    for (int i = 0; i < 8; i++) {
        int idx = tid + i * 256;
        int nl = idx >> 4, q = idx & 15;
        int n = base + nl;
        int nc = n < N_NODES ? n : N_NODES - 1;
        float4 xv = ((const float4*)xin)[nc * 16 + q];
        *(float4*)&row[nl * ROW_STRIDE + q * 4] = xv;
        float4 av = ((const float4*)g_agg)[nc * 16 + q];
        *(float4*)&row[nl * ROW_STRIDE + 64 + q * 4] = av;
    }
    __syncthreads();

    int warp = tid >> 5, lane = tid & 31;
    int g = lane >> 2, t = lane & 3;
    int r0 = warp * 16 + g;

    float acc[8][4];
    #pragma unroll
    for (int nt = 0; nt < 8; nt++) {
        float2 bv = ((const float2*)bias)[nt * 4 + t];
        acc[nt][0] = bv.x; acc[nt][1] = bv.y;
        acc[nt][2] = bv.x; acc[nt][3] = bv.y;
    }

    #pragma unroll 2
    for (int ks = 0; ks < 16; ks++) {
        int k0 = ks * 8;
        float a0f = row[r0 * ROW_STRIDE + k0 + t];
        float a1f = row[(r0 + 8) * ROW_STRIDE + k0 + t];
        float a2f = row[r0 * ROW_STRIDE + k0 + t + 4];
        float a3f = row[(r0 + 8) * ROW_STRIDE + k0 + t + 4];
        unsigned ah0 = tf32_hi(a0f), ah1 = tf32_hi(a1f);
        unsigned ah2 = tf32_hi(a2f), ah3 = tf32_hi(a3f);
        unsigned al0 = tf32_hi(a0f - __uint_as_float(ah0));
        unsigned al1 = tf32_hi(a1f - __uint_as_float(ah1));
        unsigned al2 = tf32_hi(a2f - __uint_as_float(ah2));
        unsigned al3 = tf32_hi(a3f - __uint_as_float(ah3));

        #pragma unroll
        for (int nt = 0; nt < 8; nt++) {
            float2 w0 = Ws2[(k0 + t)     * WS_STRIDE + nt * 8 + g];
            float2 w1 = Ws2[(k0 + t + 4) * WS_STRIDE + nt * 8 + g];
            unsigned bh0 = __float_as_uint(w0.x), bl0 = __float_as_uint(w0.y);
            unsigned bh1 = __float_as_uint(w1.x), bl1 = __float_as_uint(w1.y);
            mma_tf32(acc[nt], ah0, ah1, ah2, ah3, bh0, bh1);
            mma_tf32(acc[nt], ah0, ah1, ah2, ah3, bl0, bl1);
            mma_tf32(acc[nt], al0, al1, al2, al3, bh0, bh1);
        }
    }

    int n0 = base + r0;
    int n1 = n0 + 8;
    float2*  out2 = (float2*)out;
    __half2* oh2  = (__half2*)g_half;
    #pragma unroll
    for (int nt = 0; nt < 8; nt++) {
        float c0 = acc[nt][0], c1 = acc[nt][1];
        float c2 = acc[nt][2], c3 = acc[nt][3];
        if (relu) {
            c0 = fmaxf(c0, 0.f); c1 = fmaxf(c1, 0.f);
            c2 = fmaxf(c2, 0.f); c3 = fmaxf(c3, 0.f);
        }
        int colp = nt * 4 + t;
        if (n0 < N_NODES) {
            out2[n0 * 32 + colp] = make_float2(c0, c1);
            if (to_half) oh2[n0 * 32 + colp] = __floats2half2_rn(c0, c1);
        }
        if (n1 < N_NODES) {
            out2[n1 * 32 + colp] = make_float2(c2, c3);
            if (to_half) oh2[n1 * 32 + colp] = __floats2half2_rn(c2, c3);
        }
    }
}

// ---------------------------------------------------------------------------
extern "C" void kernel_launch(void* const* d_in, const int* in_sizes, int n_in,
                              void* d_out, int out_size) {
    const float* x   = (const float*)d_in[0];
    const void*  ei  = d_in[1];
    const float* W1  = (const float*)d_in[2];
    const float* b1  = (const float*)d_in[3];
    const float* W2  = (const float*)d_in[4];
    const float* b2  = (const float*)d_in[5];
    float*       out = (float*)d_out;

    float*  hbuf = nullptr;
    float2* ws1  = nullptr;
    float2* ws2  = nullptr;
    cudaGetSymbolAddress((void**)&hbuf, g_h);
    cudaGetSymbolAddress((void**)&ws1, g_ws1);
    cudaGetSymbolAddress((void**)&ws2, g_ws2);

    const int PREP_BLOCKS = (N_NODES * F / 2 + 255) / 256;       // 6250
    const int EDGE_BLOCKS = (N_EDGES + 255) / 256;               // 3125
    const int AGG_BLOCKS  = (N_NODES + 7) / 8;                   // 6250
    const int GEMM_BLOCKS = (N_NODES + TILE_M - 1) / TILE_M;     // 391
    const int SMEM_BYTES  = (TILE_M * ROW_STRIDE) * 4 + 128 * WS_STRIDE * 8;

    cudaFuncSetAttribute(gemm_kernel,
                         cudaFuncAttributeMaxDynamicSharedMemorySize, SMEM_BYTES);

    prep_kernel<<<PREP_BLOCKS, 256>>>(ei, x, W1, W2);
    scan_kernel<<<SCAN_BLOCKS, 256>>>();
    fill_kernel<<<EDGE_BLOCKS, 256>>>(ei);

    // Layer 1
    agg_kernel<<<AGG_BLOCKS, 256>>>();
    gemm_kernel<<<GEMM_BLOCKS, 256, SMEM_BYTES>>>(x, ws1, b1, hbuf,
                                                  /*relu=*/1, /*to_half=*/1);
    // Layer 2
    agg_kernel<<<AGG_BLOCKS, 256>>>();
    gemm_kernel<<<GEMM_BLOCKS, 256, SMEM_BYTES>>>(hbuf, ws2, b2, out,
                                                  /*relu=*/0, /*to_half=*/0);
}

// round 14
// speedup vs baseline: 1.0949x; 1.0949x over previous
#include <cuda_runtime.h>
#include <cuda_fp16.h>
#include <cstdint>

#define N_NODES 50000
#define N_EDGES 800000
#define F 64
#define TILE_M 128
#define ROW_STRIDE 132      // f32 stride of staged rows
#define WS_STRIDE 72        // float2 stride of W hi/lo in smem
#define SCAN_BLOCKS 196

// Scratch (allocation-free: __device__ globals)
__device__ int    g_deg[N_NODES];        // invariant: zero on entry (scan23 restores)
__device__ int    g_off[N_NODES + 1];
__device__ int    g_cur[N_NODES];
__device__ int    g_csr[N_EDGES];
__device__ int    g_bsum[SCAN_BLOCKS];
__device__ float  g_h[N_NODES * F];
__device__ float  g_agg[N_NODES * F];
__device__ __half g_half[N_NODES * F];   // fp16 mirror of gather source
__device__ float2 g_ws1[128 * 64];       // W1 hi/lo split (3xTF32)
__device__ float2 g_ws2[128 * 64];       // W2 hi/lo split

// Per-warp dtype detect: 1 cached 8B load/lane + ballot. int32 data misread
// as int64 has a random high word -> out of range almost surely.
__device__ __forceinline__ int warp_detect_is64(const void* ei) {
    int lane = threadIdx.x & 31;
    long long v = ((const long long*)ei)[lane & 15];
    unsigned m = __ballot_sync(0xffffffffu, v >= 0 && v < N_NODES);
    return m == 0xffffffffu;
}

__device__ __forceinline__ int load_idx(const void* ei, int i, int is64) {
    if (is64) return (int)((const long long*)ei)[i];
    return ((const int*)ei)[i];
}

__device__ __forceinline__ unsigned tf32_hi(float a) {
    unsigned r;
    asm("cvt.rna.tf32.f32 %0, %1;" : "=r"(r) : "f"(a));
    return r;
}

// ---------------------------------------------------------------------------
// Stream B: x -> fp16 mirror + W1/W2 hi/lo split. Independent of CSR chain.
// ---------------------------------------------------------------------------
__global__ void convert_kernel(const float* __restrict__ x,
                               const float* __restrict__ W1,
                               const float* __restrict__ W2) {
    int i = blockIdx.x * blockDim.x + threadIdx.x;
    if (i < N_NODES * F / 2) {
        float2 xv = ((const float2*)x)[i];
        ((__half2*)g_half)[i] = __floats2half2_rn(xv.x, xv.y);
    }
    if (i < 2 * 128 * 64) {
        const float* Wsel = (i < 128 * 64) ? W1 : W2;
        float2* dst = (i < 128 * 64) ? g_ws1 : g_ws2;
        int idx = i & (128 * 64 - 1);
        float w = Wsel[idx];
        unsigned hb = tf32_hi(w);
        float hf = __uint_as_float(hb);
        unsigned lb = tf32_hi(w - hf);
        dst[idx] = make_float2(hf, __uint_as_float(lb));
    }
}

// ---------------------------------------------------------------------------
// Stream A: CSR build. hist (inline detect, g_deg==0 invariant) ->
// scan1 -> scan23 (re-zeroes g_deg, zeroes g_cur) -> fill (inline detect).
// ---------------------------------------------------------------------------
__global__ void hist_kernel(const void* __restrict__ ei) {
    int is64 = warp_detect_is64(ei);
    int e = blockIdx.x * blockDim.x + threadIdx.x;
    if (e >= N_EDGES) return;
    int d = load_idx(ei, N_EDGES + e, is64);
    if ((unsigned)d < N_NODES) atomicAdd(&g_deg[d], 1);
}

__global__ void scan1_kernel() {
    __shared__ int sh[256];
    int t = threadIdx.x;
    int i = blockIdx.x * 256 + t;
    int v = (i < N_NODES) ? g_deg[i] : 0;
    sh[t] = v;
    __syncthreads();
    #pragma unroll
    for (int ofs = 1; ofs < 256; ofs <<= 1) {
        int add = (t >= ofs) ? sh[t - ofs] : 0;
        __syncthreads();
        sh[t] += add;
        __syncthreads();
    }
    if (i < N_NODES) g_off[i + 1] = sh[t];
    if (t == 255) g_bsum[blockIdx.x] = sh[255];
}

__global__ void scan23_kernel() {
    __shared__ int sh[256];
    int t = threadIdx.x;
    sh[t] = (t < SCAN_BLOCKS) ? g_bsum[t] : 0;
    __syncthreads();
    #pragma unroll
    for (int ofs = 1; ofs < 256; ofs <<= 1) {
        int add = (t >= ofs) ? sh[t - ofs] : 0;
        __syncthreads();
        sh[t] += add;
        __syncthreads();
    }
    int prefix = (blockIdx.x > 0) ? sh[blockIdx.x - 1] : 0;
    int i = blockIdx.x * 256 + t;
    if (i < N_NODES) {
        g_off[i + 1] += prefix;
        g_deg[i] = 0;     // restore hist invariant for next run
        g_cur[i] = 0;     // fill precondition
    }
    if (i == 0) g_off[0] = 0;
}

__global__ void fill_kernel(const void* __restrict__ ei) {
    int is64 = warp_detect_is64(ei);
    int e = blockIdx.x * blockDim.x + threadIdx.x;
    if (e >= N_EDGES) return;
    int s = load_idx(ei, e, is64);
    int d = load_idx(ei, N_EDGES + e, is64);
    if ((unsigned)s >= N_NODES || (unsigned)d >= N_NODES) return;
    int pos = atomicAdd(&g_cur[d], 1);
    g_csr[g_off[d] + pos] = s;
}

// ---------------------------------------------------------------------------
// CSR mean-aggregation from fp16 mirror -> g_agg (f32). (R12, proven 20us)
// ---------------------------------------------------------------------------
__global__ void __launch_bounds__(256)
agg_kernel() {
    int warp = threadIdx.x >> 5, lane = threadIdx.x & 31;
    int n = blockIdx.x * 8 + warp;
    if (n >= N_NODES) return;
    int slot  = lane >> 3;
    int fpart = lane & 7;

    const uint4* xh4 = (const uint4*)g_half;

    int e0 = g_off[n], e1 = g_off[n + 1];
    float2 a0 = make_float2(0.f, 0.f), a1 = a0, a2 = a0, a3 = a0;

    int e = e0 + slot;
    for (; e + 4 < e1; e += 8) {
        int s0 = g_csr[e];
        int s1 = g_csr[e + 4];
        uint4 u0 = xh4[s0 * 8 + fpart];
        uint4 u1 = xh4[s1 * 8 + fpart];
        float2 p;
        p = __half22float2(*(__half2*)&u0.x); a0.x += p.x; a0.y += p.y;
        p = __half22float2(*(__half2*)&u0.y); a1.x += p.x; a1.y += p.y;
        p = __half22float2(*(__half2*)&u0.z); a2.x += p.x; a2.y += p.y;
        p = __half22float2(*(__half2*)&u0.w); a3.x += p.x; a3.y += p.y;
        p = __half22float2(*(__half2*)&u1.x); a0.x += p.x; a0.y += p.y;
        p = __half22float2(*(__half2*)&u1.y); a1.x += p.x; a1.y += p.y;
        p = __half22float2(*(__half2*)&u1.z); a2.x += p.x; a2.y += p.y;
        p = __half22float2(*(__half2*)&u1.w); a3.x += p.x; a3.y += p.y;
    }
    if (e < e1) {
        int s0 = g_csr[e];
        uint4 u0 = xh4[s0 * 8 + fpart];
        float2 p;
        p = __half22float2(*(__half2*)&u0.x); a0.x += p.x; a0.y += p.y;
        p = __half22float2(*(__half2*)&u0.y); a1.x += p.x; a1.y += p.y;
        p = __half22float2(*(__half2*)&u0.z); a2.x += p.x; a2.y += p.y;
        p = __half22float2(*(__half2*)&u0.w); a3.x += p.x; a3.y += p.y;
    }

    #pragma unroll
    for (int m = 8; m <= 16; m <<= 1) {
        a0.x += __shfl_xor_sync(0xffffffffu, a0.x, m);
        a0.y += __shfl_xor_sync(0xffffffffu, a0.y, m);
        a1.x += __shfl_xor_sync(0xffffffffu, a1.x, m);
        a1.y += __shfl_xor_sync(0xffffffffu, a1.y, m);
        a2.x += __shfl_xor_sync(0xffffffffu, a2.x, m);
        a2.y += __shfl_xor_sync(0xffffffffu, a2.y, m);
        a3.x += __shfl_xor_sync(0xffffffffu, a3.x, m);
        a3.y += __shfl_xor_sync(0xffffffffu, a3.y, m);
    }

    if (slot == 0) {
        float inv = 1.0f / fmaxf((float)(e1 - e0), 1.0f);
        float4* dst = (float4*)(g_agg + n * 64 + fpart * 8);
        dst[0] = make_float4(a0.x * inv, a0.y * inv, a1.x * inv, a1.y * inv);
        dst[1] = make_float4(a2.x * inv, a2.y * inv, a3.x * inv, a3.y * inv);
    }
}

// ---------------------------------------------------------------------------
// Tensor-core GEMM (3xTF32): out = [x || agg] @ W + b (+ReLU)  (proven)
// ---------------------------------------------------------------------------
__device__ __forceinline__ void mma_tf32(float* c, unsigned a0, unsigned a1,
                                         unsigned a2, unsigned a3,
                                         unsigned b0, unsigned b1) {
    asm volatile(
        "mma.sync.aligned.m16n8k8.row.col.f32.tf32.tf32.f32 "
        "{%0,%1,%2,%3}, {%4,%5,%6,%7}, {%8,%9}, {%0,%1,%2,%3};"
        : "+f"(c[0]), "+f"(c[1]), "+f"(c[2]), "+f"(c[3])
        : "r"(a0), "r"(a1), "r"(a2), "r"(a3), "r"(b0), "r"(b1));
}

__global__ void __launch_bounds__(256)
gemm_kernel(const float* __restrict__ xin, const float2* __restrict__ Wsplit,
            const float* __restrict__ bias, float* __restrict__ out,
            int relu, int to_half) {
    extern __shared__ float sm[];
    float*  row = sm;
    float2* Ws2 = (float2*)(sm + TILE_M * ROW_STRIDE);

    int tid = threadIdx.x;

    const float4* wsrc = (const float4*)Wsplit;
    #pragma unroll
    for (int i = 0; i < 16; i++) {
        int j = tid + i * 256;
        int f2 = j * 2;
        int k = f2 >> 6, c = f2 & 63;
        *(float4*)&Ws2[k * WS_STRIDE + c] = wsrc[j];
    }

    int base = blockIdx.x * TILE_M;
    #pragma unroll
    for (int i = 0; i < 8; i++) {
        int idx = tid + i * 256;
        int nl = idx >> 4, q = idx & 15;
        int n = base + nl;
        int nc = n < N_NODES ? n : N_NODES - 1;
        float4 xv = ((const float4*)xin)[nc * 16 + q];
        *(float4*)&row[nl * ROW_STRIDE + q * 4] = xv;
        float4 av = ((const float4*)g_agg)[nc * 16 + q];
        *(float4*)&row[nl * ROW_STRIDE + 64 + q * 4] = av;
    }
    __syncthreads();

    int warp = tid >> 5, lane = tid & 31;
    int g = lane >> 2, t = lane & 3;
    int r0 = warp * 16 + g;

    float acc[8][4];
    #pragma unroll
    for (int nt = 0; nt < 8; nt++) {
        float2 bv = ((const float2*)bias)[nt * 4 + t];
        acc[nt][0] = bv.x; acc[nt][1] = bv.y;
        acc[nt][2] = bv.x; acc[nt][3] = bv.y;
    }

    #pragma unroll 2
    for (int ks = 0; ks < 16; ks++) {
        int k0 = ks * 8;
        float a0f = row[r0 * ROW_STRIDE + k0 + t];
        float a1f = row[(r0 + 8) * ROW_STRIDE + k0 + t];
        float a2f = row[r0 * ROW_STRIDE + k0 + t + 4];
        float a3f = row[(r0 + 8) * ROW_STRIDE + k0 + t + 4];
        unsigned ah0 = tf32_hi(a0f), ah1 = tf32_hi(a1f);
        unsigned ah2 = tf32_hi(a2f), ah3 = tf32_hi(a3f);
        unsigned al0 = tf32_hi(a0f - __uint_as_float(ah0));
        unsigned al1 = tf32_hi(a1f - __uint_as_float(ah1));
        unsigned al2 = tf32_hi(a2f - __uint_as_float(ah2));
        unsigned al3 = tf32_hi(a3f - __uint_as_float(ah3));

        #pragma unroll
        for (int nt = 0; nt < 8; nt++) {
            float2 w0 = Ws2[(k0 + t)     * WS_STRIDE + nt * 8 + g];
            float2 w1 = Ws2[(k0 + t + 4) * WS_STRIDE + nt * 8 + g];
            unsigned bh0 = __float_as_uint(w0.x), bl0 = __float_as_uint(w0.y);
            unsigned bh1 = __float_as_uint(w1.x), bl1 = __float_as_uint(w1.y);
            mma_tf32(acc[nt], ah0, ah1, ah2, ah3, bh0, bh1);
            mma_tf32(acc[nt], ah0, ah1, ah2, ah3, bl0, bl1);
            mma_tf32(acc[nt], al0, al1, al2, al3, bh0, bh1);
        }
    }

    int n0 = base + r0;
    int n1 = n0 + 8;
    float2*  out2 = (float2*)out;
    __half2* oh2  = (__half2*)g_half;
    #pragma unroll
    for (int nt = 0; nt < 8; nt++) {
        float c0 = acc[nt][0], c1 = acc[nt][1];
        float c2 = acc[nt][2], c3 = acc[nt][3];
        if (relu) {
            c0 = fmaxf(c0, 0.f); c1 = fmaxf(c1, 0.f);
            c2 = fmaxf(c2, 0.f); c3 = fmaxf(c3, 0.f);
        }
        int colp = nt * 4 + t;
        if (n0 < N_NODES) {
            out2[n0 * 32 + colp] = make_float2(c0, c1);
            if (to_half) oh2[n0 * 32 + colp] = __floats2half2_rn(c0, c1);
        }
        if (n1 < N_NODES) {
            out2[n1 * 32 + colp] = make_float2(c2, c3);
            if (to_half) oh2[n1 * 32 + colp] = __floats2half2_rn(c2, c3);
        }
    }
}

// ---------------------------------------------------------------------------
// Launch: stream B (convert) overlaps the CSR chain on the capture stream.
// Streams/events created once outside capture; fork/join via events is
// graph-capture legal.
// ---------------------------------------------------------------------------
extern "C" void kernel_launch(void* const* d_in, const int* in_sizes, int n_in,
                              void* d_out, int out_size) {
    const float* x   = (const float*)d_in[0];
    const void*  ei  = d_in[1];
    const float* W1  = (const float*)d_in[2];
    const float* b1  = (const float*)d_in[3];
    const float* W2  = (const float*)d_in[4];
    const float* b2  = (const float*)d_in[5];
    float*       out = (float*)d_out;

    float*  hbuf = nullptr;
    float2* ws1  = nullptr;
    float2* ws2  = nullptr;
    cudaGetSymbolAddress((void**)&hbuf, g_h);
    cudaGetSymbolAddress((void**)&ws1, g_ws1);
    cudaGetSymbolAddress((void**)&ws2, g_ws2);

    static cudaStream_t sB = nullptr;
    static cudaEvent_t evFork = nullptr, evJoin = nullptr;
    if (!sB) {
        cudaStreamCreateWithFlags(&sB, cudaStreamNonBlocking);
        cudaEventCreateWithFlags(&evFork, cudaEventDisableTiming);
        cudaEventCreateWithFlags(&evJoin, cudaEventDisableTiming);
    }

    const int CONV_BLOCKS = (N_NODES * F / 2 + 255) / 256;       // 6250
    const int EDGE_BLOCKS = (N_EDGES + 255) / 256;               // 3125
    const int AGG_BLOCKS  = (N_NODES + 7) / 8;                   // 6250
    const int GEMM_BLOCKS = (N_NODES + TILE_M - 1) / TILE_M;     // 391
    const int SMEM_BYTES  = (TILE_M * ROW_STRIDE) * 4 + 128 * WS_STRIDE * 8;

    cudaFuncSetAttribute(gemm_kernel,
                         cudaFuncAttributeMaxDynamicSharedMemorySize, SMEM_BYTES);

    // Fork: convert on stream B, CSR chain on the capture (default) stream.
    cudaEventRecord(evFork, 0);
    cudaStreamWaitEvent(sB, evFork, 0);
    convert_kernel<<<CONV_BLOCKS, 256, 0, sB>>>(x, W1, W2);
    cudaEventRecord(evJoin, sB);

    hist_kernel<<<EDGE_BLOCKS, 256>>>(ei);
    scan1_kernel<<<SCAN_BLOCKS, 256>>>();
    scan23_kernel<<<SCAN_BLOCKS, 256>>>();
    fill_kernel<<<EDGE_BLOCKS, 256>>>(ei);

    // Join before aggregation (needs g_half) and gemm (needs g_ws*).
    cudaStreamWaitEvent(0, evJoin, 0);

    // Layer 1
    agg_kernel<<<AGG_BLOCKS, 256>>>();
    gemm_kernel<<<GEMM_BLOCKS, 256, SMEM_BYTES>>>(x, ws1, b1, hbuf,
                                                  /*relu=*/1, /*to_half=*/1);
    // Layer 2
    agg_kernel<<<AGG_BLOCKS, 256>>>();
    gemm_kernel<<<GEMM_BLOCKS, 256, SMEM_BYTES>>>(hbuf, ws2, b2, out,
                                                  /*relu=*/0, /*to_half=*/0);
}